// round 11
// baseline (speedup 1.0000x reference)
#include <cuda_runtime.h>
#include <cstdint>

#define C64    64
#define HW     224
#define HP     226
#define NB     8
#define NPIX   (NB * HW * HW)
#define EPS_BN 1e-5f
#define LEAK   0.1f
#define CEILV  255.0f

#define NTILE  3584            /* 8b * 112 rowpair * 2 colseg * 2 oc-half */
#define NCTA2  296             /* 2 CTAs per SM */
#define NTHR   224             /* 7 warps, each m32 x n32 */

// SMEM float-index layout (per CTA)
#define SM_BIAS 0              /* 64 floats */
#define SM_RED  64             /* 128 floats: sum[64], ssq[64] */
#define SM_B    192            /* 72*32*8 = 18432 floats (this CTA's oc half) */
#define SM_A    18624          /* 2 bufs x (4 rows * 114 px * 8 ch) */
#define ABUF    3648           /* floats per A buffer */
#define AROW    912            /* 114 px * 8 floats */
#define SM_FLTS (18624 + 2 * ABUF)
#define SMEM_DYN (SM_FLTS * 4) /* 103680 B -> 2 CTAs/SM */

// permutation within each 8-channel group: slot = (c&3)*2 + (c>>2)
#define PERM64(c) (((c) & ~7) | (((c) & 3) << 1) | (((c) >> 2) & 1))

// ---------------- device scratch ----------------
__device__ __align__(16) float  g_xpad[NB * HP * HP * C64];  // padded NHWC, permuted ch
__device__ __align__(16) float  g_wB[72 * 64 * 8];           // [kstep][o][slot8]
__device__ double g_sum[C64];
__device__ double g_ssq[C64];
__device__ float  g_scale[C64];
__device__ float  g_shift[C64];

static __device__ __forceinline__ uint32_t tf32_rna(float x) {
    uint32_t u;
    asm("cvt.rna.tf32.f32 %0, %1;" : "=r"(u) : "f"(x));
    return u;
}
static __device__ __forceinline__ uint32_t fu(float x) { return __float_as_uint(x); }

static __device__ __forceinline__ void mma8(float* d, const uint32_t* a,
                                            const uint32_t* b) {
    asm volatile(
        "mma.sync.aligned.m16n8k8.row.col.f32.tf32.tf32.f32 "
        "{%0,%1,%2,%3},{%4,%5,%6,%7},{%8,%9},{%0,%1,%2,%3};"
        : "+f"(d[0]), "+f"(d[1]), "+f"(d[2]), "+f"(d[3])
        : "r"(a[0]), "r"(a[1]), "r"(a[2]), "r"(a[3]), "r"(b[0]), "r"(b[1]));
}
static __device__ __forceinline__ void cp16(uint32_t dst, const void* src) {
    asm volatile("cp.async.cg.shared.global [%0], [%1], 16;"
                 :: "r"(dst), "l"(src));
}

// ---------------- kernel: fold 3x3-ternary + 1x1, emit permuted tf32 -----
__global__ void fold_k(const float* __restrict__ w1x1,
                       const float* __restrict__ w_bin) {
    int t = blockIdx.x * 256 + threadIdx.x;
    if (t < C64) { g_sum[t] = 0.0; g_ssq[t] = 0.0; }
    if (t >= 64 * 9 * 64) return;
    int o = t & 63;
    int k = (t >> 6) % 9;        // tap
    int i = t / 576;             // in channel
    float s = 0.f;
    #pragma unroll 8
    for (int m = 0; m < 64; ++m)
        s += w1x1[o * 64 + m] * w_bin[(m * 64 + i) * 9 + k];
    int q8 = i >> 3, c8 = i & 7;
    int slot = (c8 & 3) * 2 + (c8 >> 2);
    g_wB[((q8 * 9 + k) * 64 + o) * 8 + slot] = __uint_as_float(tf32_rna(s));
}

// ---------------- kernel: zero padded border ----------------
__global__ void pad_zero() {
    int p = blockIdx.x;      // 0..899
    int b = blockIdx.y;
    int hp, wp;
    if (p < 226)      { hp = 0;   wp = p; }
    else if (p < 452) { hp = 225; wp = p - 226; }
    else { int q = p - 452; hp = 1 + (q >> 1); wp = (q & 1) * 225; }
    g_xpad[(((size_t)b * HP + hp) * HP + wp) * 64 + threadIdx.x] = 0.f;
}

// ---------------- kernel: NCHW -> padded NHWC, tf32-rounded, permuted ----
__global__ void pad_tr(const float* __restrict__ x) {
    __shared__ float s[64][33];
    int lx = threadIdx.x, ly = threadIdx.y;   // 32, 8
    int w0 = blockIdx.x * 32, h = blockIdx.y, b = blockIdx.z;
    #pragma unroll
    for (int i = 0; i < 8; ++i) {
        int c = i * 8 + ly;
        s[c][lx] = x[(((size_t)b * 64 + c) * HW + h) * HW + w0 + lx];
    }
    __syncthreads();
    float* dst = g_xpad + (((size_t)b * HP + h + 1) * HP + w0 + 1) * 64;
    #pragma unroll
    for (int jj = 0; jj < 8; ++jj) {
        int f = jj * 256 + ly * 32 + lx;
        int ch = f & 63, px = f >> 6;
        dst[(size_t)px * 64 + PERM64(ch)] = __uint_as_float(tf32_rna(s[ch][px]));
    }
}

// ---------------- kernel: tf32 mma conv + BN stats, 2 CTAs/SM ------------
// 296 persistent CTAs x 224 thr. CTA tile = 2 rows x 112 px x 32 oc
// (oc half = bid&1). 7 warps, warp tile m32 x n32 (acc 32 regs, 8B LDS/MMA).
// K: 8 stages of 8 ch; A double-buffered cp.async (two-sync pattern).
__global__ __launch_bounds__(NTHR, 2)
void conv_mma(const float* __restrict__ bias, float* __restrict__ out) {
    extern __shared__ __align__(16) float sm[];
    float* Bs = sm + SM_B;
    float* As = sm + SM_A;
    const int tid = threadIdx.x;
    const int lane = tid & 31, wm = tid >> 5;     // 7 m-warps
    const int gr = lane >> 2, gc = lane & 3;
    const int nh = blockIdx.x & 1;                // oc half (const per CTA)
    const uint32_t a_smem = (uint32_t)__cvta_generic_to_shared(As);

    // this CTA's 32-oc half of the weights -> SMEM once
    for (int i = tid; i < 4608; i += NTHR) {
        int ks = i >> 6, rem = i & 63;
        int op = rem >> 1, c4 = rem & 1;
        ((float4*)Bs)[i] =
            ((const float4*)g_wB)[((ks * 64 + nh * 32 + op) << 1) + c4];
    }
    if (tid < 64) sm[SM_BIAS + tid] = bias[tid];
    if (tid < 128) sm[SM_RED + tid] = 0.f;

    // hoisted per-thread cp.async offsets (912 cp16 per stage)
    uint32_t srcF[5], dstB[5];
    #pragma unroll
    for (int k = 0; k < 5; ++k) {
        int i = tid + k * NTHR;
        if (i < 912) {
            int r = i / 228, rem = i % 228;
            int px = rem >> 1, c4 = rem & 1;
            srcF[k] = (uint32_t)((r * HP + px) * 64 + c4 * 4);
            dstB[k] = (uint32_t)((r * AROW + px * 8 + c4 * 4) * 4);
        }
    }
    const int ncp = (tid < 16) ? 5 : 4;

    // A-fragment bases per m-subtile (warp covers m16 blocks wm*2, wm*2+1)
    uint32_t fbase[2];
    #pragma unroll
    for (int ms = 0; ms < 2; ++ms) {
        int mt  = wm * 2 + ms;            // 0..13
        int row = mt / 7;                 // output row within pair
        int pxl = (mt % 7) * 16;          // px within 112 segment
        fbase[ms] = (uint32_t)(row * AROW + (pxl + gr) * 8 + gc * 2);
    }
    const int bfrag = gr * 8 + gc * 2;

    const int ntiles = (NTILE - blockIdx.x + NCTA2 - 1) / NCTA2;
    const int nstage = ntiles * 8;

    auto issue = [&](int g) {
        int t = (g >> 3) * NCTA2 + blockIdx.x;
        int q8 = g & 7;
        int u = t >> 1;                   // drop oc-half bit
        int seg = u & 1, v = u >> 1;
        int rp = v % 112, b = v / 112;
        int h0 = rp * 2;                  // padded row base = h0
        const float* xb = g_xpad
            + (((size_t)(b * HP + h0) * HP) + seg * 112) * 64 + q8 * 8;
        uint32_t dst = a_smem + (uint32_t)(g & 1) * (ABUF * 4);
        #pragma unroll
        for (int k = 0; k < 5; ++k)
            if (k < ncp) cp16(dst + dstB[k], xb + srcF[k]);
        asm volatile("cp.async.commit_group;");
    };

    float ps[4][2], qs[4][2];   // per-thread BN partials
    #pragma unroll
    for (int ns = 0; ns < 4; ++ns)
        ps[ns][0] = ps[ns][1] = qs[ns][0] = qs[ns][1] = 0.f;

    float acc[2][4][4];

    issue(0);

    for (int g = 0; g < nstage; ++g) {
        if (g + 1 < nstage) {
            __syncthreads();              // stage g-1 readers done (buf reuse)
            issue(g + 1);
            asm volatile("cp.async.wait_group 1;");
        } else {
            asm volatile("cp.async.wait_group 0;");
        }
        __syncthreads();                  // buffer g&1 visible

        const int q8 = g & 7;
        if (q8 == 0) {
            #pragma unroll
            for (int ms = 0; ms < 2; ++ms)
                #pragma unroll
                for (int ns = 0; ns < 4; ++ns)
                    #pragma unroll
                    for (int q2 = 0; q2 < 4; ++q2) acc[ms][ns][q2] = 0.f;
        }

        const float* Ab = As + (g & 1) * ABUF;
        const float* Bq = Bs + q8 * 2304 + bfrag;   // 9 taps * 256 floats
        #pragma unroll
        for (int kh = 0; kh < 3; ++kh) {
            #pragma unroll
            for (int kw = 0; kw < 3; ++kw) {
                uint32_t A[2][4];
                #pragma unroll
                for (int ms = 0; ms < 2; ++ms) {
                    const float* ap = Ab + fbase[ms] + kh * AROW + kw * 8;
                    float2 u = *(const float2*)ap;
                    float2 v = *(const float2*)(ap + 64);
                    A[ms][0] = fu(u.x); A[ms][1] = fu(v.x);
                    A[ms][2] = fu(u.y); A[ms][3] = fu(v.y);
                }
                const float* bp = Bq + (kh * 3 + kw) * 256;
                #pragma unroll
                for (int ns = 0; ns < 4; ++ns) {
                    float2 bv = *(const float2*)(bp + ns * 64);
                    uint32_t Bf[2] = { fu(bv.x), fu(bv.y) };
                    mma8(acc[0][ns], A[0], Bf);
                    mma8(acc[1][ns], A[1], Bf);
                }
            }
        }

        if (q8 == 7) {
            // epilogue: + bias, NCHW store, BN partials
            int t = (g >> 3) * NCTA2 + blockIdx.x;
            int u2 = t >> 1;
            int seg = u2 & 1, v2 = u2 >> 1;
            int rp = v2 % 112, b = v2 / 112;
            const size_t chstr = (size_t)HW * HW;
            float* obb = out + ((size_t)b * 64) * chstr;
            #pragma unroll
            for (int ms = 0; ms < 2; ++ms) {
                int mt  = wm * 2 + ms;
                int row = mt / 7;
                int pxg = seg * 112 + (mt % 7) * 16 + gr;
                float* ob = obb + (size_t)(rp * 2 + row) * HW + pxg;
                #pragma unroll
                for (int ns = 0; ns < 4; ++ns) {
                    int o0 = nh * 32 + ns * 8 + gc * 2;
                    float b0 = sm[SM_BIAS + o0], b1 = sm[SM_BIAS + o0 + 1];
                    float y0 = acc[ms][ns][0] + b0;
                    float y1 = acc[ms][ns][1] + b1;
                    float y2 = acc[ms][ns][2] + b0;
                    float y3 = acc[ms][ns][3] + b1;
                    float* p = ob + (size_t)o0 * chstr;
                    p[0]         = y0;
                    p[chstr]     = y1;
                    p[8]         = y2;
                    p[chstr + 8] = y3;
                    ps[ns][0] += y0 + y2;  qs[ns][0] += y0 * y0 + y2 * y2;
                    ps[ns][1] += y1 + y3;  qs[ns][1] += y1 * y1 + y3 * y3;
                }
            }
        }
    }

    // BN partial reduction: regs -> shared -> global doubles
    #pragma unroll
    for (int ns = 0; ns < 4; ++ns) {
        int o0 = nh * 32 + ns * 8 + gc * 2;
        atomicAdd(&sm[SM_RED + o0],          ps[ns][0]);
        atomicAdd(&sm[SM_RED + o0 + 1],      ps[ns][1]);
        atomicAdd(&sm[SM_RED + 64 + o0],     qs[ns][0]);
        atomicAdd(&sm[SM_RED + 64 + o0 + 1], qs[ns][1]);
    }
    __syncthreads();
    if (tid < 64) {
        float s = sm[SM_RED + tid], q = sm[SM_RED + 64 + tid];
        if (s != 0.f || q != 0.f) {
            atomicAdd(&g_sum[tid], (double)s);
            atomicAdd(&g_ssq[tid], (double)q);
        }
    }
}

// ---------------- kernel: finalize BN ----------------
__global__ void stats_k(const float* __restrict__ gamma,
                        const float* __restrict__ beta) {
    int c = threadIdx.x;
    if (c >= C64) return;
    double m = g_sum[c] / (double)NPIX;
    double v = g_ssq[c] / (double)NPIX - m * m;
    float a = gamma[c] * rsqrtf((float)v + EPS_BN);
    g_scale[c] = a;
    g_shift[c] = beta[c] - (float)m * a;
}

// ---------------- kernel: normalize + leaky relu + clamp ----------------
__global__ void act_k(float* __restrict__ out) {
    int idx = blockIdx.x * blockDim.x + threadIdx.x;
    const int total4 = NB * C64 * HW * HW / 4;
    if (idx >= total4) return;
    int plane = (idx * 4) / (HW * HW);
    int c = plane & 63;
    float a = g_scale[c], sh = g_shift[c];
    float4 v = ((float4*)out)[idx];
    float* vp = &v.x;
    #pragma unroll
    for (int p = 0; p < 4; ++p) {
        float y = a * vp[p] + sh;
        y = (y >= 0.f) ? y : LEAK * y;
        y = fminf(fmaxf(y, 0.f), CEILV);
        vp[p] = y;
    }
    ((float4*)out)[idx] = v;
}

// ---------------- launch ----------------
extern "C" void kernel_launch(void* const* d_in, const int* in_sizes, int n_in,
                              void* d_out, int out_size) {
    const float* x     = (const float*)d_in[0];
    const float* w_bin = (const float*)d_in[1];
    const float* w1x1  = (const float*)d_in[2];
    const float* b1x1  = (const float*)d_in[3];
    const float* gamma = (const float*)d_in[4];
    const float* beta  = (const float*)d_in[5];
    float* out = (float*)d_out;

    cudaFuncSetAttribute(conv_mma, cudaFuncAttributeMaxDynamicSharedMemorySize,
                         SMEM_DYN);

    fold_k<<<(64 * 9 * 64 + 255) / 256, 256>>>(w1x1, w_bin);
    pad_zero<<<dim3(900, NB), 64>>>();
    pad_tr<<<dim3(7, HW, NB), dim3(32, 8)>>>(x);
    conv_mma<<<NCTA2, NTHR, SMEM_DYN>>>(b1x1, out);
    stats_k<<<1, 64>>>(gamma, beta);
    int total4 = NB * C64 * HW * HW / 4;
    act_k<<<(total4 + 255) / 256, 256>>>(out);
}

// round 12
// speedup vs baseline: 1.1058x; 1.1058x over previous
#include <cuda_runtime.h>
#include <cstdint>

#define C64    64
#define HW     224
#define HP     226
#define NB     8
#define NPIX   (NB * HW * HW)
#define EPS_BN 1e-5f
#define LEAK   0.1f
#define CEILV  255.0f

#define NTILE  1792            /* 8 b * 224 rows; tile = full row, 224px x 64oc */
#define NCTA   148
#define NTHR   448             /* 14 warps: 7 m-pairs x 2 n */

// SMEM float-index layout
#define SM_BIAS 0              /* 64 floats */
#define SM_RED  64             /* 128 floats: sum[64], ssq[64] */
#define SM_B    192            /* 72*64*8 = 36864 floats */
#define SM_A    37056          /* 7 pairs x 3 bufs x 864 floats */
#define ABUFP   864            /* per pair-buffer: 3 rows * 36 px * 8 ch */
#define AROWP   288            /* 36 px * 8 floats */
#define SM_FLTS (37056 + 7 * 3 * ABUFP)
#define SMEM_DYN (SM_FLTS * 4) /* 220800 B */

// permutation within each 8-channel group: slot = (c&3)*2 + (c>>2)
#define PERM64(c) (((c) & ~7) | (((c) & 3) << 1) | (((c) >> 2) & 1))

// ---------------- device scratch ----------------
__device__ __align__(16) float  g_xpad[NB * HP * HP * C64];  // padded NHWC, permuted ch
__device__ __align__(16) float  g_wB[72 * 64 * 8];           // [kstep][o][slot8]
__device__ double g_sum[C64];
__device__ double g_ssq[C64];
__device__ float  g_scale[C64];
__device__ float  g_shift[C64];

static __device__ __forceinline__ uint32_t tf32_rna(float x) {
    uint32_t u;
    asm("cvt.rna.tf32.f32 %0, %1;" : "=r"(u) : "f"(x));
    return u;
}
static __device__ __forceinline__ uint32_t fu(float x) { return __float_as_uint(x); }

static __device__ __forceinline__ void mma8(float* d, const uint32_t* a,
                                            const uint32_t* b) {
    asm volatile(
        "mma.sync.aligned.m16n8k8.row.col.f32.tf32.tf32.f32 "
        "{%0,%1,%2,%3},{%4,%5,%6,%7},{%8,%9},{%0,%1,%2,%3};"
        : "+f"(d[0]), "+f"(d[1]), "+f"(d[2]), "+f"(d[3])
        : "r"(a[0]), "r"(a[1]), "r"(a[2]), "r"(a[3]), "r"(b[0]), "r"(b[1]));
}
static __device__ __forceinline__ void cp16(uint32_t dst, const void* src) {
    asm volatile("cp.async.cg.shared.global [%0], [%1], 16;"
                 :: "r"(dst), "l"(src));
}
static __device__ __forceinline__ void pair_bar(int id) {
    asm volatile("bar.sync %0, 64;" :: "r"(id) : "memory");
}

// ---------------- kernel: fold 3x3-ternary + 1x1, emit permuted tf32 -----
__global__ void fold_k(const float* __restrict__ w1x1,
                       const float* __restrict__ w_bin) {
    int t = blockIdx.x * 256 + threadIdx.x;
    if (t < C64) { g_sum[t] = 0.0; g_ssq[t] = 0.0; }
    if (t >= 64 * 9 * 64) return;
    int o = t & 63;
    int k = (t >> 6) % 9;        // tap
    int i = t / 576;             // in channel
    float s = 0.f;
    #pragma unroll 8
    for (int m = 0; m < 64; ++m)
        s += w1x1[o * 64 + m] * w_bin[(m * 64 + i) * 9 + k];
    int q8 = i >> 3, c8 = i & 7;
    int slot = (c8 & 3) * 2 + (c8 >> 2);
    g_wB[((q8 * 9 + k) * 64 + o) * 8 + slot] = __uint_as_float(tf32_rna(s));
}

// ---------------- kernel: zero padded border ----------------
__global__ void pad_zero() {
    int p = blockIdx.x;      // 0..899
    int b = blockIdx.y;
    int hp, wp;
    if (p < 226)      { hp = 0;   wp = p; }
    else if (p < 452) { hp = 225; wp = p - 226; }
    else { int q = p - 452; hp = 1 + (q >> 1); wp = (q & 1) * 225; }
    g_xpad[(((size_t)b * HP + hp) * HP + wp) * 64 + threadIdx.x] = 0.f;
}

// ---------------- kernel: NCHW -> padded NHWC, tf32-rounded, permuted ----
__global__ void pad_tr(const float* __restrict__ x) {
    __shared__ float s[64][33];
    int lx = threadIdx.x, ly = threadIdx.y;   // 32, 8
    int w0 = blockIdx.x * 32, h = blockIdx.y, b = blockIdx.z;
    #pragma unroll
    for (int i = 0; i < 8; ++i) {
        int c = i * 8 + ly;
        s[c][lx] = x[(((size_t)b * 64 + c) * HW + h) * HW + w0 + lx];
    }
    __syncthreads();
    float* dst = g_xpad + (((size_t)b * HP + h + 1) * HP + w0 + 1) * 64;
    #pragma unroll
    for (int jj = 0; jj < 8; ++jj) {
        int f = jj * 256 + ly * 32 + lx;
        int ch = f & 63, px = f >> 6;
        dst[(size_t)px * 64 + PERM64(ch)] = __uint_as_float(tf32_rna(s[ch][px]));
    }
}

// ---------------- kernel: pair-decoupled tf32 mma conv + BN stats --------
// Persistent 148 CTAs x 448 thr. Tile = full row 224px x 64oc; 8 stages of
// 8 ch. Each 2-warp m-pair stages its own 34px x 3row A window (triple
// buffered) and syncs ONLY via bar.sync(pair,64) -> no CTA-wide stage
// barrier, pairs free-run and mutually hide copy latency.
__global__ __launch_bounds__(NTHR, 1)
void conv_mma(const float* __restrict__ bias, float* __restrict__ out) {
    extern __shared__ __align__(16) float sm[];
    float* Bs = sm + SM_B;
    float* As = sm + SM_A;
    const int tid = threadIdx.x;
    const int lane = tid & 31, wid = tid >> 5;
    const int wn = wid & 1, wm = wid >> 1;       // 7 m-pairs x 2 n-warps
    const int ptid = tid & 63;                    // thread-in-pair
    const int gr = lane >> 2, gc = lane & 3;
    const uint32_t a_smem = (uint32_t)__cvta_generic_to_shared(As);

    // weights + bias -> SMEM once; zero reduction slots
    for (int i = tid; i < 9216; i += NTHR)
        ((float4*)Bs)[i] = ((const float4*)g_wB)[i];
    if (tid < 64) sm[SM_BIAS + tid] = bias[tid];
    if (tid < 128) sm[SM_RED + tid] = 0.f;
    __syncthreads();    // B/bias visible to all; only CTA-wide bar until end

    // hoisted per-pair-thread cp.async offsets (204 cp16 per pair-stage)
    uint32_t srcF[4], dstB[4];
    #pragma unroll
    for (int k = 0; k < 4; ++k) {
        int i = ptid + k * 64;
        if (i < 204) {
            int r = i / 68, rem = i % 68;
            int px = rem >> 1, c4 = rem & 1;
            srcF[k] = (uint32_t)((r * HP + wm * 32 + px) * 64 + c4 * 4);
            dstB[k] = (uint32_t)((wm * (3 * ABUFP) + r * AROWP + px * 8
                                  + c4 * 4) * 4);
        }
    }
    const int ncp = (ptid < 12) ? 4 : 3;

    const int pbase = wm * (3 * ABUFP);
    const int bfrag = (wn * 32 + gr) * 8 + gc * 2;

    const int ntiles = (NTILE - blockIdx.x + NCTA - 1) / NCTA;
    const int nstage = ntiles * 8;

    auto issue = [&](int g) {
        int t = (g >> 3) * NCTA + blockIdx.x;
        int q8 = g & 7;
        const float* xrow = g_xpad
            + (((size_t)(t / 224) * HP + (t % 224)) * HP) * 64 + q8 * 8;
        uint32_t dst = a_smem + (uint32_t)(g % 3) * (ABUFP * 4);
        #pragma unroll
        for (int k = 0; k < 4; ++k)
            if (k < ncp) cp16(dst + dstB[k], xrow + srcF[k]);
        asm volatile("cp.async.commit_group;");
    };

    float ps[4][2], qs[4][2];   // per-thread BN partials
    #pragma unroll
    for (int ns = 0; ns < 4; ++ns)
        ps[ns][0] = ps[ns][1] = qs[ns][0] = qs[ns][1] = 0.f;

    float acc[2][4][4];

    issue(0);

    for (int g = 0; g < nstage; ++g) {
        if (g + 1 < nstage) {
            issue(g + 1);
            asm volatile("cp.async.wait_group 1;");
        } else {
            asm volatile("cp.async.wait_group 0;");
        }
        pair_bar(wm + 1);      // both warps of pair: copy g visible

        const int q8 = g & 7;
        if (q8 == 0) {
            #pragma unroll
            for (int ms = 0; ms < 2; ++ms)
                #pragma unroll
                for (int ns = 0; ns < 4; ++ns)
                    #pragma unroll
                    for (int q2 = 0; q2 < 4; ++q2) acc[ms][ns][q2] = 0.f;
        }

        const float* Ab = As + pbase + (g % 3) * ABUFP;
        const float* Bq = Bs + q8 * 4608 + bfrag;
        #pragma unroll
        for (int kh = 0; kh < 3; ++kh) {
            #pragma unroll
            for (int kw = 0; kw < 3; ++kw) {
                uint32_t A[2][4];
                #pragma unroll
                for (int ms = 0; ms < 2; ++ms) {
                    const float* ap = Ab + kh * AROWP
                        + (ms * 16 + gr + kw) * 8 + gc * 2;
                    float2 u = *(const float2*)ap;
                    float2 v = *(const float2*)(ap + 64);
                    A[ms][0] = fu(u.x); A[ms][1] = fu(v.x);
                    A[ms][2] = fu(u.y); A[ms][3] = fu(v.y);
                }
                const float* bp = Bq + (kh * 3 + kw) * 512;
                #pragma unroll
                for (int ns = 0; ns < 4; ++ns) {
                    float2 bv = *(const float2*)(bp + ns * 64);
                    uint32_t Bf[2] = { fu(bv.x), fu(bv.y) };
                    mma8(acc[0][ns], A[0], Bf);
                    mma8(acc[1][ns], A[1], Bf);
                }
            }
        }

        if (q8 == 7) {
            // epilogue: + bias, NCHW store, BN partials
            int t = (g >> 3) * NCTA + blockIdx.x;
            int b = t / 224, h = t % 224;
            const size_t chstr = (size_t)HW * HW;
            const int pxb = wm * 32 + gr;
            const int ob  = wn * 32 + gc * 2;
            float* obase = out + ((size_t)b * 64) * chstr + (size_t)h * HW;
            #pragma unroll
            for (int ms = 0; ms < 2; ++ms) {
                #pragma unroll
                for (int ns = 0; ns < 4; ++ns) {
                    int o0 = ob + ns * 8;
                    float b0 = sm[SM_BIAS + o0], b1 = sm[SM_BIAS + o0 + 1];
                    float y0 = acc[ms][ns][0] + b0;
                    float y1 = acc[ms][ns][1] + b1;
                    float y2 = acc[ms][ns][2] + b0;
                    float y3 = acc[ms][ns][3] + b1;
                    float* p = obase + (size_t)o0 * chstr + pxb + ms * 16;
                    p[0]         = y0;
                    p[chstr]     = y1;
                    p[8]         = y2;
                    p[chstr + 8] = y3;
                    ps[ns][0] += y0 + y2;  qs[ns][0] += y0 * y0 + y2 * y2;
                    ps[ns][1] += y1 + y3;  qs[ns][1] += y1 * y1 + y3 * y3;
                }
            }
        }
    }

    // BN partial reduction: regs -> shared -> global doubles
    #pragma unroll
    for (int ns = 0; ns < 4; ++ns) {
        int o0 = wn * 32 + ns * 8 + gc * 2;
        atomicAdd(&sm[SM_RED + o0],          ps[ns][0]);
        atomicAdd(&sm[SM_RED + o0 + 1],      ps[ns][1]);
        atomicAdd(&sm[SM_RED + 64 + o0],     qs[ns][0]);
        atomicAdd(&sm[SM_RED + 64 + o0 + 1], qs[ns][1]);
    }
    __syncthreads();
    if (tid < 64) {
        atomicAdd(&g_sum[tid], (double)sm[SM_RED + tid]);
        atomicAdd(&g_ssq[tid], (double)sm[SM_RED + 64 + tid]);
    }
}

// ---------------- kernel: finalize BN ----------------
__global__ void stats_k(const float* __restrict__ gamma,
                        const float* __restrict__ beta) {
    int c = threadIdx.x;
    if (c >= C64) return;
    double m = g_sum[c] / (double)NPIX;
    double v = g_ssq[c] / (double)NPIX - m * m;
    float a = gamma[c] * rsqrtf((float)v + EPS_BN);
    g_scale[c] = a;
    g_shift[c] = beta[c] - (float)m * a;
}

// ---------------- kernel: normalize + leaky relu + clamp ----------------
__global__ void act_k(float* __restrict__ out) {
    int idx = blockIdx.x * blockDim.x + threadIdx.x;
    const int total4 = NB * C64 * HW * HW / 4;
    if (idx >= total4) return;
    int plane = (idx * 4) / (HW * HW);
    int c = plane & 63;
    float a = g_scale[c], sh = g_shift[c];
    float4 v = ((float4*)out)[idx];
    float* vp = &v.x;
    #pragma unroll
    for (int p = 0; p < 4; ++p) {
        float y = a * vp[p] + sh;
        y = (y >= 0.f) ? y : LEAK * y;
        y = fminf(fmaxf(y, 0.f), CEILV);
        vp[p] = y;
    }
    ((float4*)out)[idx] = v;
}

// ---------------- launch ----------------
extern "C" void kernel_launch(void* const* d_in, const int* in_sizes, int n_in,
                              void* d_out, int out_size) {
    const float* x     = (const float*)d_in[0];
    const float* w_bin = (const float*)d_in[1];
    const float* w1x1  = (const float*)d_in[2];
    const float* b1x1  = (const float*)d_in[3];
    const float* gamma = (const float*)d_in[4];
    const float* beta  = (const float*)d_in[5];
    float* out = (float*)d_out;

    cudaFuncSetAttribute(conv_mma, cudaFuncAttributeMaxDynamicSharedMemorySize,
                         SMEM_DYN);

    fold_k<<<(64 * 9 * 64 + 255) / 256, 256>>>(w1x1, w_bin);
    pad_zero<<<dim3(900, NB), 64>>>();
    pad_tr<<<dim3(7, HW, NB), dim3(32, 8)>>>(x);
    conv_mma<<<NCTA, NTHR, SMEM_DYN>>>(b1x1, out);
    stats_k<<<1, 64>>>(gamma, beta);
    int total4 = NB * C64 * HW * HW / 4;
    act_k<<<(total4 + 255) / 256, 256>>>(out);
}